// round 8
// baseline (speedup 1.0000x reference)
#include <cuda_runtime.h>
#include <cuda_bf16.h>
#include <cuda_fp16.h>
#include <mma.h>

using namespace nvcuda;

#define F 128
#define N_NODES_MAX 100000
#define N_ROWS_PAD 100096  // 1564 * 64 (GEMM tile M=64)

// fp16 support (only consumer is the scatter)
__device__ __half g_support_h[(size_t)N_ROWS_PAD * F];
__device__ __nv_bfloat16 g_whi[F * F];
__device__ __nv_bfloat16 g_wlo[F * F];

// ---------------------------------------------------------------------------
// W split: w -> bf16 hi/lo (16384 elems)
// ---------------------------------------------------------------------------
__global__ void wsplit_kernel(const float* __restrict__ w) {
    int i = blockIdx.x * blockDim.x + threadIdx.x;
    float f = w[i];
    __nv_bfloat16 h = __float2bfloat16_rn(f);
    g_whi[i] = h;
    g_wlo[i] = __float2bfloat16_rn(f - __bfloat162float(h));
}

// ---------------------------------------------------------------------------
// GEMM: support_h = fp16(x @ W) (BF16x3 compensated) AND out = bias (fused).
// Block 128 thr (4 warps), tile 64x128, warp tile 32x64, 3 CTAs/SM.
// x tile double-buffered via register prefetch (hides DRAM latency).
// ---------------------------------------------------------------------------
__global__ void __launch_bounds__(128, 3) gemm_bf16x3_kernel(
    const float* __restrict__ x, const float* __restrict__ bias,
    float* __restrict__ out, int n) {
    __shared__ __nv_bfloat16 xs_hi[64][40];   // 5.0 KB
    __shared__ __nv_bfloat16 xs_lo[64][40];   // 5.0 KB
    __shared__ __nv_bfloat16 ws_hi[32][136];  // 8.5 KB
    __shared__ __nv_bfloat16 ws_lo[32][136];  // 8.5 KB
    __shared__ float bs[F];                   // bias copy

    const int tid = threadIdx.x;
    const int wid = tid >> 5;
    const int lane = tid & 31;
    const int warp_m = wid & 1;
    const int warp_n = wid >> 1;
    const int row0 = blockIdx.x * 64;

    bs[tid] = __ldg(&bias[tid]);  // blockDim == 128 == F

    wmma::fragment<wmma::accumulator, 16, 16, 16, float> acc[2][4];
    #pragma unroll
    for (int i = 0; i < 2; i++)
        #pragma unroll
        for (int j = 0; j < 4; j++) wmma::fill_fragment(acc[i][j], 0.0f);

    // prefetch x tile kt=0 into registers (4 float4 per thread)
    float4 px[4];
    #pragma unroll
    for (int u = 0; u < 4; u++) {
        int i = tid + u * 128;
        int r = i >> 3;
        int c = (i & 7) * 4;
        int row = row0 + r;
        px[u] = (row < n) ? *(const float4*)&x[(size_t)row * F + c]
                          : make_float4(0.f, 0.f, 0.f, 0.f);
    }

    for (int kt = 0; kt < 4; kt++) {
        // write prefetched x tile to smem with hi/lo split
        #pragma unroll
        for (int u = 0; u < 4; u++) {
            int i = tid + u * 128;
            int r = i >> 3;
            int c = (i & 7) * 4;
            float f[4] = {px[u].x, px[u].y, px[u].z, px[u].w};
            #pragma unroll
            for (int q = 0; q < 4; q++) {
                __nv_bfloat16 h = __float2bfloat16_rn(f[q]);
                xs_hi[r][c + q] = h;
                xs_lo[r][c + q] = __float2bfloat16_rn(f[q] - __bfloat162float(h));
            }
        }
        // copy W tile (presplit bf16, L2-hot)
        #pragma unroll
        for (int i = tid; i < 512; i += 128) {
            int r = i >> 4;
            int c = (i & 15) * 8;
            size_t src = (size_t)(kt * 32 + r) * F + c;
            *(uint4*)&ws_hi[r][c] = *(const uint4*)&g_whi[src];
            *(uint4*)&ws_lo[r][c] = *(const uint4*)&g_wlo[src];
        }
        __syncthreads();

        // prefetch next x tile while mma runs on this one
        if (kt < 3) {
            #pragma unroll
            for (int u = 0; u < 4; u++) {
                int i = tid + u * 128;
                int r = i >> 3;
                int c = (i & 7) * 4;
                int row = row0 + r;
                px[u] = (row < n)
                            ? *(const float4*)&x[(size_t)row * F + (kt + 1) * 32 + c]
                            : make_float4(0.f, 0.f, 0.f, 0.f);
            }
        }

        #pragma unroll
        for (int ks = 0; ks < 2; ks++) {
            wmma::fragment<wmma::matrix_a, 16, 16, 16, __nv_bfloat16,
                           wmma::row_major> a_hi[2], a_lo[2];
            #pragma unroll
            for (int i = 0; i < 2; i++) {
                wmma::load_matrix_sync(a_hi[i],
                                       &xs_hi[warp_m * 32 + i * 16][ks * 16], 40);
                wmma::load_matrix_sync(a_lo[i],
                                       &xs_lo[warp_m * 32 + i * 16][ks * 16], 40);
            }
            #pragma unroll
            for (int j = 0; j < 4; j++) {
                wmma::fragment<wmma::matrix_b, 16, 16, 16, __nv_bfloat16,
                               wmma::row_major> b_hi, b_lo;
                wmma::load_matrix_sync(b_hi,
                                       &ws_hi[ks * 16][warp_n * 64 + j * 16], 136);
                wmma::load_matrix_sync(b_lo,
                                       &ws_lo[ks * 16][warp_n * 64 + j * 16], 136);
                #pragma unroll
                for (int i = 0; i < 2; i++) {
                    wmma::mma_sync(acc[i][j], a_hi[i], b_hi, acc[i][j]);
                    wmma::mma_sync(acc[i][j], a_hi[i], b_lo, acc[i][j]);
                    wmma::mma_sync(acc[i][j], a_lo[i], b_hi, acc[i][j]);
                }
            }
        }
        __syncthreads();
    }

    // Epilogue: stage each 16x16 frag via smem; write fp16 support AND
    // out[row] = bias (fused bias init; scatter adds on top via RED).
    float* stage = (float*)&xs_hi[0][0] + wid * 320;  // 16x20 floats per warp
    #pragma unroll
    for (int i = 0; i < 2; i++)
        #pragma unroll
        for (int j = 0; j < 4; j++) {
            wmma::store_matrix_sync(stage, acc[i][j], 20, wmma::mem_row_major);
            __syncwarp();
            int r = lane >> 1;
            int c = (lane & 1) * 8;
            int col0 = warp_n * 64 + j * 16 + c;
            float fv[8];
            __half hbuf[8];
            #pragma unroll
            for (int q = 0; q < 8; q++) {
                fv[q] = stage[r * 20 + c + q];
                hbuf[q] = __float2half_rn(fv[q]);
            }
            size_t row = (size_t)row0 + warp_m * 32 + i * 16 + r;
            *(uint4*)&g_support_h[row * F + col0] = *(uint4*)hbuf;
            if ((int)row < n) {
                float4 o0 = make_float4(bs[col0 + 0], bs[col0 + 1],
                                        bs[col0 + 2], bs[col0 + 3]);
                float4 o1 = make_float4(bs[col0 + 4], bs[col0 + 5],
                                        bs[col0 + 6], bs[col0 + 7]);
                *(float4*)&out[row * F + col0] = o0;
                *(float4*)&out[row * F + col0 + 4] = o1;
            }
            __syncwarp();
        }
}

// ---------------------------------------------------------------------------
// Edge scatter (both edge sets, one launch):
//   out[rows[e]] += support_h[cols[e]] * vals[e]
// Warp owns 32 edges: coalesced index loads + shfl broadcast.
// 8B fp16 gather per lane; one red.global.add.v4.f32 per lane per edge.
// ---------------------------------------------------------------------------
__global__ void __launch_bounds__(256) scatter_kernel(
    const float* __restrict__ vals0, const int* __restrict__ rows0,
    const int* __restrict__ cols0,
    const float* __restrict__ vals1, const int* __restrict__ rows1,
    const int* __restrict__ cols1,
    float* __restrict__ out, int E) {
    int gw = (blockIdx.x * blockDim.x + threadIdx.x) >> 5;
    int lane = threadIdx.x & 31;
    int warps_per_set = (E + 31) >> 5;
    if (gw >= 2 * warps_per_set) return;

    const float* vals;
    const int* rows;
    const int* cols;
    int wset = gw;
    if (gw < warps_per_set) {
        vals = vals0; rows = rows0; cols = cols0;
    } else {
        vals = vals1; rows = rows1; cols = cols1; wset = gw - warps_per_set;
    }
    int base = wset * 32;

    int e = base + lane;
    bool valid = e < E;
    float v = valid ? __ldg(&vals[e]) : 0.f;
    int r = valid ? __ldg(&rows[e]) : 0;
    int c = valid ? __ldg(&cols[e]) : 0;

    int cnt = min(32, E - base);
    const uint2* sup = (const uint2*)g_support_h;

    #pragma unroll 4
    for (int i = 0; i < cnt; i++) {
        int rr = __shfl_sync(0xffffffff, r, i);
        int cc = __shfl_sync(0xffffffff, c, i);
        float vv = __shfl_sync(0xffffffff, v, i);

        uint2 packed = __ldg(&sup[(size_t)cc * (F / 4) + lane]);
        float2 f01 = __half22float2(*(__half2*)&packed.x);
        float2 f23 = __half22float2(*(__half2*)&packed.y);

        float* dst = out + (size_t)rr * F + lane * 4;
        asm volatile("red.global.add.v4.f32 [%0], {%1,%2,%3,%4};"
                     :: "l"(dst), "f"(f01.x * vv), "f"(f01.y * vv),
                        "f"(f23.x * vv), "f"(f23.y * vv)
                     : "memory");
    }
}

// ---------------------------------------------------------------------------
// kernel_launch
// inputs: x, weight, bias, vals0, vals1, rows0, cols0, rows1, cols1
// ---------------------------------------------------------------------------
extern "C" void kernel_launch(void* const* d_in, const int* in_sizes, int n_in,
                              void* d_out, int out_size) {
    const float* x     = (const float*)d_in[0];
    const float* w     = (const float*)d_in[1];
    const float* bias  = (const float*)d_in[2];
    const float* vals0 = (const float*)d_in[3];
    const float* vals1 = (const float*)d_in[4];
    const int* rows0   = (const int*)d_in[5];
    const int* cols0   = (const int*)d_in[6];
    const int* rows1   = (const int*)d_in[7];
    const int* cols1   = (const int*)d_in[8];
    float* out = (float*)d_out;

    int n = in_sizes[0] / F;   // 100000
    int E = in_sizes[3];       // 600000

    // 1) W hi/lo split, then support_h = fp16(x @ W); out = bias (fused)
    wsplit_kernel<<<(F * F) / 256, 256>>>(w);
    gemm_bf16x3_kernel<<<(n + 63) / 64, 128>>>(x, bias, out, n);

    // 2) scatter both edge sets (one launch, vector reds)
    long long total_warps = 2LL * ((E + 31) / 32);
    int sblocks = (int)((total_warps * 32 + 255) / 256);
    scatter_kernel<<<sblocks, 256>>>(vals0, rows0, cols0, vals1, rows1, cols1,
                                     out, E);
}

// round 9
// speedup vs baseline: 1.8412x; 1.8412x over previous
#include <cuda_runtime.h>
#include <cuda_fp16.h>
#include <mma.h>

using namespace nvcuda;

#define F 128
#define N_NODES_MAX 100000
#define N_ROWS_PAD 100096  // 1564 * 64 (GEMM tile M=64)

// fp16 support (only consumer is the scatter)
__device__ __half g_support_h[(size_t)N_ROWS_PAD * F];
__device__ __half g_wh[F * F];  // W in fp16

// ---------------------------------------------------------------------------
// W convert: w -> fp16 (16384 elems)
// ---------------------------------------------------------------------------
__global__ void whalf_kernel(const float* __restrict__ w) {
    int i = blockIdx.x * blockDim.x + threadIdx.x;
    g_wh[i] = __float2half_rn(w[i]);
}

// ---------------------------------------------------------------------------
// GEMM: support_h[n,128] = fp16( x[n,128] @ w[128,128] ), FP16 x1, fp32 acc.
// Structure verbatim from the proven R5 kernel: block 128 thr (4 warps),
// tile 64(M) x 128(N), warp tile 32x64, K tiled 4x32, 3 CTAs/SM.
// ---------------------------------------------------------------------------
__global__ void __launch_bounds__(128, 3) gemm_fp16_kernel(
    const float* __restrict__ x, int n) {
    __shared__ __half xs[64][40];    // 5.0 KB
    __shared__ __half ws[32][136];   // 8.5 KB

    const int tid = threadIdx.x;
    const int wid = tid >> 5;
    const int lane = tid & 31;
    const int warp_m = wid & 1;   // 32-row band
    const int warp_n = wid >> 1;  // 64-col band
    const int row0 = blockIdx.x * 64;

    wmma::fragment<wmma::accumulator, 16, 16, 16, float> acc[2][4];
    #pragma unroll
    for (int i = 0; i < 2; i++)
        #pragma unroll
        for (int j = 0; j < 4; j++) wmma::fill_fragment(acc[i][j], 0.0f);

    for (int kt = 0; kt < 4; kt++) {
        // x tile 64x32: 512 float4, 4 per thread; convert to fp16
        #pragma unroll
        for (int i = tid; i < 512; i += 128) {
            int r = i >> 3;
            int c = (i & 7) * 4;
            int row = row0 + r;
            float4 v = make_float4(0.f, 0.f, 0.f, 0.f);
            if (row < n)
                v = *(const float4*)&x[(size_t)row * F + kt * 32 + c];
            __half hb[4] = {__float2half_rn(v.x), __float2half_rn(v.y),
                            __float2half_rn(v.z), __float2half_rn(v.w)};
            *(uint2*)&xs[r][c] = *(uint2*)hb;
        }
        // w tile 32x128: copy preconverted fp16 (L2-hot)
        #pragma unroll
        for (int i = tid; i < 512; i += 128) {
            int r = i >> 4;            // 16 x 8-elem chunks per row
            int c = (i & 15) * 8;
            size_t src = (size_t)(kt * 32 + r) * F + c;
            *(uint4*)&ws[r][c] = *(const uint4*)&g_wh[src];
        }
        __syncthreads();

        #pragma unroll
        for (int ks = 0; ks < 2; ks++) {  // 2 k-steps of 16
            wmma::fragment<wmma::matrix_a, 16, 16, 16, __half,
                           wmma::row_major> a[2];
            #pragma unroll
            for (int i = 0; i < 2; i++)
                wmma::load_matrix_sync(a[i],
                                       &xs[warp_m * 32 + i * 16][ks * 16], 40);
            #pragma unroll
            for (int j = 0; j < 4; j++) {
                wmma::fragment<wmma::matrix_b, 16, 16, 16, __half,
                               wmma::row_major> b;
                wmma::load_matrix_sync(b,
                                       &ws[ks * 16][warp_n * 64 + j * 16], 136);
                #pragma unroll
                for (int i = 0; i < 2; i++)
                    wmma::mma_sync(acc[i][j], a[i], b, acc[i][j]);
            }
        }
        __syncthreads();
    }

    // Epilogue (verbatim R5): stage each 16x16 frag via smem, write fp16.
    float* stage = (float*)&xs[0][0] + wid * 320;  // 16x20 floats per warp
    #pragma unroll
    for (int i = 0; i < 2; i++)
        #pragma unroll
        for (int j = 0; j < 4; j++) {
            wmma::store_matrix_sync(stage, acc[i][j], 20, wmma::mem_row_major);
            __syncwarp();
            int r = lane >> 1;
            int c = (lane & 1) * 8;
            __half hbuf[8];
            #pragma unroll
            for (int q = 0; q < 8; q++)
                hbuf[q] = __float2half_rn(stage[r * 20 + c + q]);
            size_t row = (size_t)row0 + warp_m * 32 + i * 16 + r;
            *(uint4*)&g_support_h[row * F + warp_n * 64 + j * 16 + c] =
                *(uint4*)hbuf;
            __syncwarp();
        }
}

// ---------------------------------------------------------------------------
// out[i][f] = bias[f]   (verbatim R5)
// ---------------------------------------------------------------------------
__global__ void bias_init_kernel(const float* __restrict__ bias,
                                 float* __restrict__ out, int n) {
    size_t idx = (size_t)blockIdx.x * blockDim.x + threadIdx.x;
    size_t total = (size_t)n * (F / 4);
    float4* out4 = (float4*)out;
    const float4* b4 = (const float4*)bias;
    for (size_t i = idx; i < total; i += (size_t)gridDim.x * blockDim.x) {
        out4[i] = b4[i & (F / 4 - 1)];
    }
}

// ---------------------------------------------------------------------------
// Edge scatter (verbatim R5): out[rows[e]] += support_h[cols[e]] * vals[e]
// Warp owns 32 edges: coalesced index loads + shfl broadcast.
// 8B fp16 gather per lane; one red.global.add.v4.f32 per lane per edge.
// ---------------------------------------------------------------------------
__global__ void __launch_bounds__(256) scatter_kernel(
    const float* __restrict__ vals0, const int* __restrict__ rows0,
    const int* __restrict__ cols0,
    const float* __restrict__ vals1, const int* __restrict__ rows1,
    const int* __restrict__ cols1,
    float* __restrict__ out, int E) {
    int gw = (blockIdx.x * blockDim.x + threadIdx.x) >> 5;
    int lane = threadIdx.x & 31;
    int warps_per_set = (E + 31) >> 5;
    if (gw >= 2 * warps_per_set) return;

    const float* vals;
    const int* rows;
    const int* cols;
    int wset = gw;
    if (gw < warps_per_set) {
        vals = vals0; rows = rows0; cols = cols0;
    } else {
        vals = vals1; rows = rows1; cols = cols1; wset = gw - warps_per_set;
    }
    int base = wset * 32;

    int e = base + lane;
    bool valid = e < E;
    float v = valid ? __ldg(&vals[e]) : 0.f;
    int r = valid ? __ldg(&rows[e]) : 0;
    int c = valid ? __ldg(&cols[e]) : 0;

    int cnt = min(32, E - base);
    const uint2* sup = (const uint2*)g_support_h;

    #pragma unroll 4
    for (int i = 0; i < cnt; i++) {
        int rr = __shfl_sync(0xffffffff, r, i);
        int cc = __shfl_sync(0xffffffff, c, i);
        float vv = __shfl_sync(0xffffffff, v, i);

        uint2 packed = __ldg(&sup[(size_t)cc * (F / 4) + lane]);
        float2 f01 = __half22float2(*(__half2*)&packed.x);
        float2 f23 = __half22float2(*(__half2*)&packed.y);

        float* dst = out + (size_t)rr * F + lane * 4;
        asm volatile("red.global.add.v4.f32 [%0], {%1,%2,%3,%4};"
                     :: "l"(dst), "f"(f01.x * vv), "f"(f01.y * vv),
                        "f"(f23.x * vv), "f"(f23.y * vv)
                     : "memory");
    }
}

// ---------------------------------------------------------------------------
// kernel_launch
// inputs: x, weight, bias, vals0, vals1, rows0, cols0, rows1, cols1
// ---------------------------------------------------------------------------
extern "C" void kernel_launch(void* const* d_in, const int* in_sizes, int n_in,
                              void* d_out, int out_size) {
    const float* x     = (const float*)d_in[0];
    const float* w     = (const float*)d_in[1];
    const float* bias  = (const float*)d_in[2];
    const float* vals0 = (const float*)d_in[3];
    const float* vals1 = (const float*)d_in[4];
    const int* rows0   = (const int*)d_in[5];
    const int* cols0   = (const int*)d_in[6];
    const int* rows1   = (const int*)d_in[7];
    const int* cols1   = (const int*)d_in[8];
    float* out = (float*)d_out;

    int n = in_sizes[0] / F;   // 100000
    int E = in_sizes[3];       // 600000

    // 1) W fp16 convert, then support_h = fp16(x @ W)
    whalf_kernel<<<(F * F) / 256, 256>>>(w);
    gemm_fp16_kernel<<<(n + 63) / 64, 128>>>(x, n);

    // 2) out = bias
    bias_init_kernel<<<2048, 256>>>(bias, out, n);

    // 3) scatter both edge sets (one launch, vector reds)
    long long total_warps = 2LL * ((E + 31) / 32);
    int sblocks = (int)((total_warps * 32 + 255) / 256);
    scatter_kernel<<<sblocks, 256>>>(vals0, rows0, cols0, vals1, rows1, cols1,
                                     out, E);
}